// round 15
// baseline (speedup 1.0000x reference)
#include <cuda_runtime.h>
#include <cuda_bf16.h>

// ApproxEMD: B=16, N=2048, D=3. Flash-style, fused, x-sorted, fine-grained
// exact underflow skipping, ONE persistent kernel for all 9 auction steps
// (512 co-resident blocks, software grid barrier). This round: 2-tile
// register tiling — each warp processes its 4 column-tiles as 2 pairs
// (t, t+32); the pair shares the 3 smem row loads and doubles chain ILP.
// A tile whose gap-bound proves underflow computes exact +0.0f anyway, so
// pairing an alive tile with a dead one is bit-identical to skipping it.

#define BB 16
#define NN 2048
#define BN (BB*NN)
#define EPSV 1e-9f
#define CH 128            // rows/cols per smem chunk
#define NCHUNK (NN/CH)    // 16
#define UTH (-150.0f)
#define NBLK 512

// permuted (x-sorted) copies, SoA
__device__ float g_spx[BN], g_spy[BN], g_spz[BN], g_spn[BN];   // preds
__device__ float g_slx[BN], g_sly[BN], g_slz[BN], g_slm[BN];   // labels
__device__ float g_curr2[2][BN];
__device__ float g_cost2[2][BN];
__device__ float g_SEp[NCHUNK][BN];
__device__ float g_SECp[NCHUNK][BN];
__device__ float g_Rp[NCHUNK][BN];
__device__ double g_out;
__device__ unsigned g_bar_count;   // zero-init
__device__ unsigned g_bar_gen;     // zero-init; monotonic across replays

__constant__ float c_EFL[9] = {   // ef * log2(e)
    -16384.0f * 1.4426950408889634f, -4096.0f * 1.4426950408889634f,
    -1024.0f * 1.4426950408889634f,  -256.0f * 1.4426950408889634f,
    -64.0f * 1.4426950408889634f,    -16.0f * 1.4426950408889634f,
    -4.0f * 1.4426950408889634f,     -1.0f * 1.4426950408889634f,
    -0.25f * 1.4426950408889634f
};

typedef unsigned long long u64;

__device__ __forceinline__ float ex2f(float x) {
    float r;
    asm("ex2.approx.f32 %0, %1;" : "=f"(r) : "f"(x));
    return r;
}
__device__ __forceinline__ u64 pk(float lo, float hi) {
    u64 d;
    asm("mov.b64 %0, {%1, %2};" : "=l"(d)
        : "r"(__float_as_uint(lo)), "r"(__float_as_uint(hi)));
    return d;
}
__device__ __forceinline__ void upk(u64 v, float& lo, float& hi) {
    unsigned a, b;
    asm("mov.b64 {%0, %1}, %2;" : "=r"(a), "=r"(b) : "l"(v));
    lo = __uint_as_float(a); hi = __uint_as_float(b);
}
__device__ __forceinline__ u64 fma2(u64 a, u64 b, u64 c) {
    u64 d;
    asm("fma.rn.f32x2 %0, %1, %2, %3;" : "=l"(d) : "l"(a), "l"(b), "l"(c));
    return d;
}
__device__ __forceinline__ u64 add2(u64 a, u64 b) {
    u64 d;
    asm("add.rn.f32x2 %0, %1, %2;" : "=l"(d) : "l"(a), "l"(b));
    return d;
}
__device__ __forceinline__ u64 mul2(u64 a, u64 b) {
    u64 d;
    asm("mul.rn.f32x2 %0, %1, %2;" : "=l"(d) : "l"(a), "l"(b));
    return d;
}

// Software grid barrier: valid because all NBLK blocks are co-resident.
__device__ __forceinline__ void grid_sync() {
    __syncthreads();
    if (threadIdx.x == 0) {
        __threadfence();
        unsigned gen = *(volatile unsigned*)&g_bar_gen;
        if (atomicAdd(&g_bar_count, 1u) == NBLK - 1u) {
            g_bar_count = 0;
            __threadfence();
            *(volatile unsigned*)&g_bar_gen = gen + 1u;
        } else {
            while (*(volatile unsigned*)&g_bar_gen == gen) __nanosleep(64);
        }
        __threadfence();
    }
    __syncthreads();
}

// Bitonic sort by x per (side, batch); gather into SoA + init state.
__global__ void __launch_bounds__(1024) k_sort(
    const float* __restrict__ preds, const float* __restrict__ labels) {
    const int side = blockIdx.x;       // 0 = preds, 1 = labels
    const int b = blockIdx.y;
    const float* src = side ? labels : preds;
    __shared__ u64 s[NN];
    const int tid = threadIdx.x;

    for (int i = tid; i < NN; i += 1024) {
        float x = src[((size_t)b * NN + i) * 3];
        unsigned u = __float_as_uint(x);
        u = (u & 0x80000000u) ? ~u : (u | 0x80000000u);  // orderable transform
        s[i] = ((u64)u << 32) | (unsigned)i;
    }
    for (int k = 2; k <= NN; k <<= 1) {
        for (int j = k >> 1; j > 0; j >>= 1) {
            __syncthreads();
            for (int i = tid; i < NN; i += 1024) {
                int ixj = i ^ j;
                if (ixj > i) {
                    bool up = ((i & k) == 0);
                    u64 a = s[i], c = s[ixj];
                    if ((a > c) == up) { s[i] = c; s[ixj] = a; }
                }
            }
        }
    }
    __syncthreads();
    for (int i = tid; i < NN; i += 1024) {
        int idx = (int)(s[i] & 0xFFFFFFFFu);
        const float* q = src + ((size_t)b * NN + idx) * 3;
        float x = q[0], y = q[1], z = q[2];
        int o = b * NN + i;
        if (side) {
            g_slx[o] = x; g_sly[o] = y; g_slz[o] = z;
            g_slm[o] = x*x + y*y + z*z;
            g_cost2[0][o] = 1.0f;
        } else {
            g_spx[o] = x; g_spy[o] = y; g_spz[o] = z;
            g_spn[o] = x*x + y*y + z*z;
            g_curr2[0][o] = 1.0f;
#pragma unroll
            for (int ch = 0; ch < NCHUNK; ch++) g_Rp[ch][o] = 0.0f;
        }
    }
    if (side == 0 && b == 0 && tid == 0) g_out = 0.0;
}

// Persistent kernel: all 9 steps + ef0 closed form.
// grid (NCHUNK, 2, BB) = 512 blocks, 256 threads.
__global__ void __launch_bounds__(256, 4) k_persist() {
    const int b = blockIdx.z;
    const int chunk = blockIdx.x;
    const int half = blockIdx.y;
    __shared__ ulonglong2 sD1[CH/2];  // (m2*vx pair, m2*vy pair)
    __shared__ ulonglong2 sD2[CH/2];  // (m2*vz pair, w pair)
    __shared__ u64        sS [CH/2];  // scalar pair (currency or g)
    __shared__ float      sred[256];

    const int lane = threadIdx.x & 31;
    const int w = threadIdx.x >> 5;

    for (int s = 0; s < 9; s++) {
        const float efl = c_EFL[s];
        const float m2 = -2.0f * efl;
        const int par = s & 1;

        // ---------------- col phase ----------------
        if (threadIdx.x < CH) {
            const int j = threadIdx.x;
            const int n = b * NN + chunk * CH + j;
            float r = 0.0f;
#pragma unroll
            for (int ch = 0; ch < NCHUNK; ch++) r += g_Rp[ch][n];
            float cu = g_curr2[par][n];
            float c = fmaxf(cu - cu * r, 0.0f);
            g_curr2[1 - par][n] = c;   // duplicate identical write across halves
            float* p1 = (float*)sD1; float* p2 = (float*)sD2; float* pc = (float*)sS;
            int q = j >> 1, h = j & 1;
            p1[q * 4 + h]     = m2 * g_spx[n];
            p1[q * 4 + 2 + h] = m2 * g_spy[n];
            p2[q * 4 + h]     = m2 * g_spz[n];
            p2[q * 4 + 2 + h] = efl * g_spn[n];
            pc[q * 2 + h]     = c;
        }
        __syncthreads();

        {
            const int rb = b * NN + chunk * CH;
            const float rlo = g_spx[rb], rhi = g_spx[rb + CH - 1];
#pragma unroll
            for (int k = 0; k < 2; k++) {
                const int tA = w + 8 * half + 16 * k;     // tiles 0..31
                const int tB = tA + 32;                   // tiles 32..63
                const int cbA = b * NN + tA * 32, cbB = b * NN + tB * 32;
                const int mA = cbA + lane, mB = cbB + lane;
                float gapA = fmaxf(0.0f, fmaxf(rlo - g_slx[cbA + 31], g_slx[cbA] - rhi));
                float gapB = fmaxf(0.0f, fmaxf(rlo - g_slx[cbB + 31], g_slx[cbB] - rhi));
                bool aA = (efl * gapA * gapA >= UTH);
                bool aB = (efl * gapB * gapB >= UTH);
                float e0A = 0, e1A = 0, c0A = 0, c1A = 0;
                float e0B = 0, e1B = 0, c0B = 0, c1B = 0;
                if (aA || aB) {
                    const u64 lxA = pk(g_slx[mA], g_slx[mA]);
                    const u64 lyA = pk(g_sly[mA], g_sly[mA]);
                    const u64 lzA = pk(g_slz[mA], g_slz[mA]);
                    const float wbA_ = efl * g_slm[mA];
                    const u64 wbA = pk(wbA_, wbA_);
                    const u64 lxB = pk(g_slx[mB], g_slx[mB]);
                    const u64 lyB = pk(g_sly[mB], g_sly[mB]);
                    const u64 lzB = pk(g_slz[mB], g_slz[mB]);
                    const float wbB_ = efl * g_slm[mB];
                    const u64 wbB = pk(wbB_, wbB_);
                    u64 sEA = 0ull, sECA = 0ull, sEB = 0ull, sECB = 0ull;
#pragma unroll 4
                    for (int i = 0; i < CH / 2; i++) {
                        ulonglong2 A = sD1[i];
                        ulonglong2 Bv = sD2[i];
                        u64 cc = sS[i];
                        u64 argA = fma2(Bv.x, lzA, fma2(A.y, lyA,
                                        fma2(A.x, lxA, add2(Bv.y, wbA))));
                        u64 argB = fma2(Bv.x, lzB, fma2(A.y, lyB,
                                        fma2(A.x, lxB, add2(Bv.y, wbB))));
                        float a0, a1, b0, b1;
                        upk(argA, a0, a1); upk(argB, b0, b1);
                        u64 eA = pk(ex2f(a0), ex2f(a1));
                        u64 eB = pk(ex2f(b0), ex2f(b1));
                        sEA = add2(sEA, eA); sECA = fma2(eA, cc, sECA);
                        sEB = add2(sEB, eB); sECB = fma2(eB, cc, sECB);
                    }
                    upk(sEA, e0A, e1A); upk(sECA, c0A, c1A);
                    upk(sEB, e0B, e1B); upk(sECB, c0B, c1B);
                }
                g_SEp [chunk][mA] = e0A + e1A;
                g_SECp[chunk][mA] = c0A + c1A;
                g_SEp [chunk][mB] = e0B + e1B;
                g_SECp[chunk][mB] = c0B + c1B;
            }
        }
        grid_sync();

        // ---------------- row phase ----------------
        if (threadIdx.x < CH) {
            const int j = threadIdx.x;
            const int m = b * NN + chunk * CH + j;
            float se = 0.0f, sec = 0.0f;
#pragma unroll
            for (int ch = 0; ch < NCHUNK; ch++) {
                se += g_SEp[ch][m];
                sec += g_SECp[ch][m];
            }
            float cost = g_cost2[par][m];
            float s1 = cost * se;
            float s2 = cost * sec / (s1 + EPSV);
            float wt = fminf(cost / (s2 + EPSV), 1.0f);
            float gv = cost * wt / (s1 + EPSV);
            g_cost2[1 - par][m] = fmaxf(cost - s2 * wt, 0.0f);  // dup write
            float* p1 = (float*)sD1; float* p2 = (float*)sD2; float* pg = (float*)sS;
            int q = j >> 1, h = j & 1;
            p1[q * 4 + h]     = m2 * g_slx[m];
            p1[q * 4 + 2 + h] = m2 * g_sly[m];
            p2[q * 4 + h]     = m2 * g_slz[m];
            p2[q * 4 + 2 + h] = efl * g_slm[m];
            pg[q * 2 + h]     = gv;
        }
        __syncthreads();

        {
            const int cb = b * NN + chunk * CH;
            const float clo = g_slx[cb], chi = g_slx[cb + CH - 1];
            const float* cu = g_curr2[1 - par];
            float v = 0.0f;
#pragma unroll
            for (int k = 0; k < 2; k++) {
                const int tA = w + 8 * half + 16 * k;
                const int tB = tA + 32;
                const int pbA = b * NN + tA * 32, pbB = b * NN + tB * 32;
                const int nA = pbA + lane, nB = pbB + lane;
                float gapA = fmaxf(0.0f, fmaxf(g_spx[pbA] - chi, clo - g_spx[pbA + 31]));
                float gapB = fmaxf(0.0f, fmaxf(g_spx[pbB] - chi, clo - g_spx[pbB + 31]));
                bool aA = (efl * gapA * gapA >= UTH);
                bool aB = (efl * gapB * gapB >= UTH);
                float rsA = 0.0f, rsB = 0.0f;
                if (aA || aB) {
                    const u64 pxA = pk(g_spx[nA], g_spx[nA]);
                    const u64 pyA = pk(g_spy[nA], g_spy[nA]);
                    const u64 pzA = pk(g_spz[nA], g_spz[nA]);
                    const float wpA_ = efl * g_spn[nA];
                    const u64 wpA = pk(wpA_, wpA_);
                    const u64 pxB = pk(g_spx[nB], g_spx[nB]);
                    const u64 pyB = pk(g_spy[nB], g_spy[nB]);
                    const u64 pzB = pk(g_spz[nB], g_spz[nB]);
                    const float wpB_ = efl * g_spn[nB];
                    const u64 wpB = pk(wpB_, wpB_);
                    u64 rAccA = 0ull, oAccA = 0ull, rAccB = 0ull, oAccB = 0ull;
#pragma unroll 4
                    for (int i = 0; i < CH / 2; i++) {
                        ulonglong2 A = sD1[i];
                        ulonglong2 Bv = sD2[i];
                        u64 g2 = sS[i];
                        u64 argA = fma2(Bv.x, pzA, fma2(A.y, pyA,
                                        fma2(A.x, pxA, add2(Bv.y, wpA))));
                        u64 argB = fma2(Bv.x, pzB, fma2(A.y, pyB,
                                        fma2(A.x, pxB, add2(Bv.y, wpB))));
                        float a0, a1, b0, b1;
                        upk(argA, a0, a1); upk(argB, b0, b1);
                        u64 eA = pk(ex2f(a0), ex2f(a1));
                        u64 eB = pk(ex2f(b0), ex2f(b1));
                        u64 tA2 = mul2(eA, g2);
                        u64 tB2 = mul2(eB, g2);
                        rAccA = add2(rAccA, tA2); oAccA = fma2(tA2, argA, oAccA);
                        rAccB = add2(rAccB, tB2); oAccB = fma2(tB2, argB, oAccB);
                    }
                    float r0, r1, o0, o1;
                    upk(rAccA, r0, r1); upk(oAccA, o0, o1);
                    rsA = r0 + r1;
                    v += cu[nA] * (o0 + o1);
                    upk(rAccB, r0, r1); upk(oAccB, o0, o1);
                    rsB = r0 + r1;
                    v += cu[nB] * (o0 + o1);
                }
                g_Rp[chunk][nA] = rsA;
                g_Rp[chunk][nB] = rsB;
            }
            v *= (1.0f / efl);
#pragma unroll
            for (int off = 16; off > 0; off >>= 1)
                v += __shfl_down_sync(0xFFFFFFFFu, v, off);
            if (lane == 0) sred[w] = v;
            __syncthreads();
            if (threadIdx.x == 0) {
                float sv = 0.0f;
#pragma unroll
                for (int i = 0; i < 8; i++) sv += sred[i];
                atomicAdd(&g_out, (double)sv);
            }
        }
        grid_sync();
    }

    // ---------------- ef==0 step: closed form, one block per batch ----------
    if (chunk == 0 && half == 0) {
        const int tid = threadIdx.x;
        float C = 0, CP = 0, CX = 0, CY = 0, CZ = 0;
        for (int n = tid; n < NN; n += 256) {
            int idx = b * NN + n;
            float r = 0.0f;
#pragma unroll
            for (int ch = 0; ch < NCHUNK; ch++) r += g_Rp[ch][idx];
            float cu = g_curr2[1][idx];
            float c = fmaxf(cu - cu * r, 0.0f);
            C += c; CP += c * g_spn[idx];
            CX += c * g_spx[idx]; CY += c * g_spy[idx]; CZ += c * g_spz[idx];
        }
        auto reduce = [&](float v) -> float {
            sred[tid] = v; __syncthreads();
            for (int st = 128; st > 0; st >>= 1) {
                if (tid < st) sred[tid] += sred[tid + st];
                __syncthreads();
            }
            float r = sred[0]; __syncthreads();
            return r;
        };
        float Cs = reduce(C);
        float CPs = reduce(CP);
        float CXs = reduce(CX);
        float CYs = reduce(CY);
        float CZs = reduce(CZ);

        float G = 0, GL = 0, GX = 0, GY = 0, GZ = 0;
        for (int m = tid; m < NN; m += 256) {
            int idx = b * NN + m;
            float cost = g_cost2[1][idx];   // cost after step 8
            float s1 = cost * (float)NN;
            float s2 = cost * Cs / (s1 + EPSV);
            float wt = fminf(cost / (s2 + EPSV), 1.0f);
            float g = cost * wt / (s1 + EPSV);
            G += g; GL += g * g_slm[idx];
            GX += g * g_slx[idx]; GY += g * g_sly[idx]; GZ += g * g_slz[idx];
        }
        float Gs = reduce(G);
        float GLs = reduce(GL);
        float GXs = reduce(GX);
        float GYs = reduce(GY);
        float GZs = reduce(GZ);

        if (tid == 0) {
            double ob = (double)CPs * Gs + (double)Cs * GLs
                      - 2.0 * ((double)CXs * GXs + (double)CYs * GYs + (double)CZs * GZs);
            atomicAdd(&g_out, ob);
        }
    }
}

__global__ void k_write(float* out) {
    out[0] = (float)g_out;
}

extern "C" void kernel_launch(void* const* d_in, const int* in_sizes, int n_in,
                              void* d_out, int out_size) {
    const float* preds = (const float*)d_in[0];
    const float* labels = (const float*)d_in[1];
    float* out = (float*)d_out;

    k_sort<<<dim3(2, BB), 1024>>>(preds, labels);
    k_persist<<<dim3(NCHUNK, 2, BB), 256>>>();   // 512 co-resident blocks
    k_write<<<1, 1>>>(out);
}

// round 16
// speedup vs baseline: 1.7515x; 1.7515x over previous
#include <cuda_runtime.h>
#include <cuda_bf16.h>

// ApproxEMD: B=16, N=2048, D=3. Flash-style, fused, x-sorted, fine-grained
// exact underflow skipping, ONE persistent kernel for all 9 auction steps.
// All cross-block dependencies are intra-batch, so synchronization uses 16
// independent per-batch barriers (32 blocks each, padded state) instead of a
// 512-block grid barrier: less contention, and batches proceed decoupled.
// Phase bodies are the proven R13 versions (455.7us). Blocks co-resident:
// 512 <= 148*4 via __launch_bounds__(256,4).
// Tile skip: both sets x-sorted; per (warp, 32-col tile) efl*gap(x)^2 < -150
// proves every exp2 underflows to exactly +0.0f (matches fp32 reference).

#define BB 16
#define NN 2048
#define BN (BB*NN)
#define EPSV 1e-9f
#define CH 128            // rows/cols per smem chunk
#define NCHUNK (NN/CH)    // 16
#define UTH (-150.0f)
#define BLK_PER_B 32      // blocks per batch (NCHUNK * 2)

// permuted (x-sorted) copies, SoA
__device__ float g_spx[BN], g_spy[BN], g_spz[BN], g_spn[BN];   // preds
__device__ float g_slx[BN], g_sly[BN], g_slz[BN], g_slm[BN];   // labels
__device__ float g_curr2[2][BN];
__device__ float g_cost2[2][BN];
__device__ float g_SEp[NCHUNK][BN];
__device__ float g_SECp[NCHUNK][BN];
__device__ float g_Rp[NCHUNK][BN];
__device__ double g_out;
__device__ unsigned g_bar_count[BB * 32];   // zero-init; slot b*32, 128B apart
__device__ unsigned g_bar_gen[BB * 32];     // zero-init; monotonic across replays

__constant__ float c_EFL[9] = {   // ef * log2(e)
    -16384.0f * 1.4426950408889634f, -4096.0f * 1.4426950408889634f,
    -1024.0f * 1.4426950408889634f,  -256.0f * 1.4426950408889634f,
    -64.0f * 1.4426950408889634f,    -16.0f * 1.4426950408889634f,
    -4.0f * 1.4426950408889634f,     -1.0f * 1.4426950408889634f,
    -0.25f * 1.4426950408889634f
};

typedef unsigned long long u64;

__device__ __forceinline__ float ex2f(float x) {
    float r;
    asm("ex2.approx.f32 %0, %1;" : "=f"(r) : "f"(x));
    return r;
}
__device__ __forceinline__ u64 pk(float lo, float hi) {
    u64 d;
    asm("mov.b64 %0, {%1, %2};" : "=l"(d)
        : "r"(__float_as_uint(lo)), "r"(__float_as_uint(hi)));
    return d;
}
__device__ __forceinline__ void upk(u64 v, float& lo, float& hi) {
    unsigned a, b;
    asm("mov.b64 {%0, %1}, %2;" : "=r"(a), "=r"(b) : "l"(v));
    lo = __uint_as_float(a); hi = __uint_as_float(b);
}
__device__ __forceinline__ u64 fma2(u64 a, u64 b, u64 c) {
    u64 d;
    asm("fma.rn.f32x2 %0, %1, %2, %3;" : "=l"(d) : "l"(a), "l"(b), "l"(c));
    return d;
}
__device__ __forceinline__ u64 add2(u64 a, u64 b) {
    u64 d;
    asm("add.rn.f32x2 %0, %1, %2;" : "=l"(d) : "l"(a), "l"(b));
    return d;
}
__device__ __forceinline__ u64 mul2(u64 a, u64 b) {
    u64 d;
    asm("mul.rn.f32x2 %0, %1, %2;" : "=l"(d) : "l"(a), "l"(b));
    return d;
}

// Per-batch barrier: only the 32 blocks of batch b participate. Valid
// because all blocks are co-resident (512 <= 148*4).
__device__ __forceinline__ void batch_sync(int b) {
    __syncthreads();
    if (threadIdx.x == 0) {
        __threadfence();
        volatile unsigned* genp = &g_bar_gen[b * 32];
        unsigned gen = *genp;
        if (atomicAdd(&g_bar_count[b * 32], 1u) == BLK_PER_B - 1u) {
            g_bar_count[b * 32] = 0;
            __threadfence();
            *genp = gen + 1u;
        } else {
            while (*genp == gen) __nanosleep(32);
        }
        __threadfence();
    }
    __syncthreads();
}

// Bitonic sort by x per (side, batch); gather into SoA + init state.
__global__ void __launch_bounds__(1024) k_sort(
    const float* __restrict__ preds, const float* __restrict__ labels) {
    const int side = blockIdx.x;       // 0 = preds, 1 = labels
    const int b = blockIdx.y;
    const float* src = side ? labels : preds;
    __shared__ u64 s[NN];
    const int tid = threadIdx.x;

    for (int i = tid; i < NN; i += 1024) {
        float x = src[((size_t)b * NN + i) * 3];
        unsigned u = __float_as_uint(x);
        u = (u & 0x80000000u) ? ~u : (u | 0x80000000u);  // orderable transform
        s[i] = ((u64)u << 32) | (unsigned)i;
    }
    for (int k = 2; k <= NN; k <<= 1) {
        for (int j = k >> 1; j > 0; j >>= 1) {
            __syncthreads();
            for (int i = tid; i < NN; i += 1024) {
                int ixj = i ^ j;
                if (ixj > i) {
                    bool up = ((i & k) == 0);
                    u64 a = s[i], c = s[ixj];
                    if ((a > c) == up) { s[i] = c; s[ixj] = a; }
                }
            }
        }
    }
    __syncthreads();
    for (int i = tid; i < NN; i += 1024) {
        int idx = (int)(s[i] & 0xFFFFFFFFu);
        const float* q = src + ((size_t)b * NN + idx) * 3;
        float x = q[0], y = q[1], z = q[2];
        int o = b * NN + i;
        if (side) {
            g_slx[o] = x; g_sly[o] = y; g_slz[o] = z;
            g_slm[o] = x*x + y*y + z*z;
            g_cost2[0][o] = 1.0f;
        } else {
            g_spx[o] = x; g_spy[o] = y; g_spz[o] = z;
            g_spn[o] = x*x + y*y + z*z;
            g_curr2[0][o] = 1.0f;
#pragma unroll
            for (int ch = 0; ch < NCHUNK; ch++) g_Rp[ch][o] = 0.0f;
        }
    }
    if (side == 0 && b == 0 && tid == 0) g_out = 0.0;
}

// Persistent kernel: all 9 steps + ef0 closed form.
// grid (NCHUNK, 2, BB) = 512 blocks, 256 threads.
__global__ void __launch_bounds__(256, 4) k_persist() {
    const int b = blockIdx.z;
    const int chunk = blockIdx.x;
    const int half = blockIdx.y;
    __shared__ ulonglong2 sD1[CH/2];  // (m2*vx pair, m2*vy pair)
    __shared__ ulonglong2 sD2[CH/2];  // (m2*vz pair, w pair)
    __shared__ u64        sS [CH/2];  // scalar pair (currency or g)
    __shared__ float      sred[256];

    const int lane = threadIdx.x & 31;
    const int w = threadIdx.x >> 5;

    for (int s = 0; s < 9; s++) {
        const float efl = c_EFL[s];
        const float m2 = -2.0f * efl;
        const int par = s & 1;

        // ---------------- col phase ----------------
        if (threadIdx.x < CH) {
            const int j = threadIdx.x;
            const int n = b * NN + chunk * CH + j;
            float r = 0.0f;
#pragma unroll
            for (int ch = 0; ch < NCHUNK; ch++) r += g_Rp[ch][n];
            float cu = g_curr2[par][n];
            float c = fmaxf(cu - cu * r, 0.0f);
            g_curr2[1 - par][n] = c;   // duplicate identical write across halves
            float* p1 = (float*)sD1; float* p2 = (float*)sD2; float* pc = (float*)sS;
            int q = j >> 1, h = j & 1;
            p1[q * 4 + h]     = m2 * g_spx[n];
            p1[q * 4 + 2 + h] = m2 * g_spy[n];
            p2[q * 4 + h]     = m2 * g_spz[n];
            p2[q * 4 + 2 + h] = efl * g_spn[n];
            pc[q * 2 + h]     = c;
        }
        __syncthreads();

        {
            const int rb = b * NN + chunk * CH;
            const float rlo = g_spx[rb], rhi = g_spx[rb + CH - 1];
#pragma unroll
            for (int k = 0; k < 4; k++) {
                const int t = w + 8 * half + 16 * k;      // ctile 0..63
                const int cb = b * NN + t * 32;
                const int m = cb + lane;
                float clo = g_slx[cb], chi = g_slx[cb + 31];
                float gap = fmaxf(0.0f, fmaxf(rlo - chi, clo - rhi));
                float e0 = 0, e1 = 0, c0 = 0, c1 = 0;
                if (efl * gap * gap >= UTH) {             // else all E == +0.0f
                    const u64 lxb = pk(g_slx[m], g_slx[m]);
                    const u64 lyb = pk(g_sly[m], g_sly[m]);
                    const u64 lzb = pk(g_slz[m], g_slz[m]);
                    const float wb = efl * g_slm[m];
                    const u64 wbb = pk(wb, wb);
                    u64 sE = 0ull, sEC = 0ull;
#pragma unroll 8
                    for (int i = 0; i < CH / 2; i++) {
                        ulonglong2 A = sD1[i];
                        ulonglong2 Bv = sD2[i];
                        u64 cc = sS[i];
                        u64 arg = fma2(Bv.x, lzb, fma2(A.y, lyb,
                                       fma2(A.x, lxb, add2(Bv.y, wbb))));
                        float a0, a1; upk(arg, a0, a1);
                        u64 e = pk(ex2f(a0), ex2f(a1));
                        sE = add2(sE, e);
                        sEC = fma2(e, cc, sEC);
                    }
                    upk(sE, e0, e1); upk(sEC, c0, c1);
                }
                g_SEp [chunk][m] = e0 + e1;
                g_SECp[chunk][m] = c0 + c1;
            }
        }
        batch_sync(b);

        // ---------------- row phase ----------------
        if (threadIdx.x < CH) {
            const int j = threadIdx.x;
            const int m = b * NN + chunk * CH + j;
            float se = 0.0f, sec = 0.0f;
#pragma unroll
            for (int ch = 0; ch < NCHUNK; ch++) {
                se += g_SEp[ch][m];
                sec += g_SECp[ch][m];
            }
            float cost = g_cost2[par][m];
            float s1 = cost * se;
            float s2 = cost * sec / (s1 + EPSV);
            float wt = fminf(cost / (s2 + EPSV), 1.0f);
            float gv = cost * wt / (s1 + EPSV);
            g_cost2[1 - par][m] = fmaxf(cost - s2 * wt, 0.0f);  // dup write
            float* p1 = (float*)sD1; float* p2 = (float*)sD2; float* pg = (float*)sS;
            int q = j >> 1, h = j & 1;
            p1[q * 4 + h]     = m2 * g_slx[m];
            p1[q * 4 + 2 + h] = m2 * g_sly[m];
            p2[q * 4 + h]     = m2 * g_slz[m];
            p2[q * 4 + 2 + h] = efl * g_slm[m];
            pg[q * 2 + h]     = gv;
        }
        __syncthreads();

        {
            const int cb = b * NN + chunk * CH;
            const float clo = g_slx[cb], chi = g_slx[cb + CH - 1];
            const float* cu = g_curr2[1 - par];
            float v = 0.0f;
#pragma unroll
            for (int k = 0; k < 4; k++) {
                const int t = w + 8 * half + 16 * k;      // pred tile 0..63
                const int pb = b * NN + t * 32;
                const int n = pb + lane;
                float rlo = g_spx[pb], rhi = g_spx[pb + 31];
                float gap = fmaxf(0.0f, fmaxf(rlo - chi, clo - rhi));
                float rsum = 0.0f;
                if (efl * gap * gap >= UTH) {
                    const u64 pxb = pk(g_spx[n], g_spx[n]);
                    const u64 pyb = pk(g_spy[n], g_spy[n]);
                    const u64 pzb = pk(g_spz[n], g_spz[n]);
                    const float wp = efl * g_spn[n];
                    const u64 wpb = pk(wp, wp);
                    u64 rAcc = 0ull, oAcc = 0ull;
#pragma unroll 8
                    for (int i = 0; i < CH / 2; i++) {
                        ulonglong2 A = sD1[i];
                        ulonglong2 Bv = sD2[i];
                        u64 g2 = sS[i];
                        u64 arg = fma2(Bv.x, pzb, fma2(A.y, pyb,
                                       fma2(A.x, pxb, add2(Bv.y, wpb))));
                        float a0, a1; upk(arg, a0, a1);
                        u64 e = pk(ex2f(a0), ex2f(a1));
                        u64 tt = mul2(e, g2);
                        rAcc = add2(rAcc, tt);
                        oAcc = fma2(tt, arg, oAcc);   // accumulates efl * t * d
                    }
                    float r0, r1, o0, o1;
                    upk(rAcc, r0, r1); upk(oAcc, o0, o1);
                    rsum = r0 + r1;
                    v += cu[n] * (o0 + o1);
                }
                g_Rp[chunk][n] = rsum;
            }
            v *= (1.0f / efl);
#pragma unroll
            for (int off = 16; off > 0; off >>= 1)
                v += __shfl_down_sync(0xFFFFFFFFu, v, off);
            if (lane == 0) sred[w] = v;
            __syncthreads();
            if (threadIdx.x == 0) {
                float sv = 0.0f;
#pragma unroll
                for (int i = 0; i < 8; i++) sv += sred[i];
                atomicAdd(&g_out, (double)sv);
            }
        }
        batch_sync(b);
    }

    // ---------------- ef==0 step: closed form, one block per batch ----------
    if (chunk == 0 && half == 0) {
        const int tid = threadIdx.x;
        float C = 0, CP = 0, CX = 0, CY = 0, CZ = 0;
        for (int n = tid; n < NN; n += 256) {
            int idx = b * NN + n;
            float r = 0.0f;
#pragma unroll
            for (int ch = 0; ch < NCHUNK; ch++) r += g_Rp[ch][idx];
            float cu = g_curr2[1][idx];
            float c = fmaxf(cu - cu * r, 0.0f);
            C += c; CP += c * g_spn[idx];
            CX += c * g_spx[idx]; CY += c * g_spy[idx]; CZ += c * g_spz[idx];
        }
        auto reduce = [&](float v) -> float {
            sred[tid] = v; __syncthreads();
            for (int st = 128; st > 0; st >>= 1) {
                if (tid < st) sred[tid] += sred[tid + st];
                __syncthreads();
            }
            float r = sred[0]; __syncthreads();
            return r;
        };
        float Cs = reduce(C);
        float CPs = reduce(CP);
        float CXs = reduce(CX);
        float CYs = reduce(CY);
        float CZs = reduce(CZ);

        float G = 0, GL = 0, GX = 0, GY = 0, GZ = 0;
        for (int m = tid; m < NN; m += 256) {
            int idx = b * NN + m;
            float cost = g_cost2[1][idx];   // cost after step 8
            float s1 = cost * (float)NN;
            float s2 = cost * Cs / (s1 + EPSV);
            float wt = fminf(cost / (s2 + EPSV), 1.0f);
            float g = cost * wt / (s1 + EPSV);
            G += g; GL += g * g_slm[idx];
            GX += g * g_slx[idx]; GY += g * g_sly[idx]; GZ += g * g_slz[idx];
        }
        float Gs = reduce(G);
        float GLs = reduce(GL);
        float GXs = reduce(GX);
        float GYs = reduce(GY);
        float GZs = reduce(GZ);

        if (tid == 0) {
            double ob = (double)CPs * Gs + (double)Cs * GLs
                      - 2.0 * ((double)CXs * GXs + (double)CYs * GYs + (double)CZs * GZs);
            atomicAdd(&g_out, ob);
        }
    }
}

__global__ void k_write(float* out) {
    out[0] = (float)g_out;
}

extern "C" void kernel_launch(void* const* d_in, const int* in_sizes, int n_in,
                              void* d_out, int out_size) {
    const float* preds = (const float*)d_in[0];
    const float* labels = (const float*)d_in[1];
    float* out = (float*)d_out;

    k_sort<<<dim3(2, BB), 1024>>>(preds, labels);
    k_persist<<<dim3(NCHUNK, 2, BB), 256>>>();   // 512 co-resident blocks
    k_write<<<1, 1>>>(out);
}